// round 15
// baseline (speedup 1.0000x reference)
#include <cuda_runtime.h>
#include <cstdint>

#define NC 200000
#define NCOMP 3
#define NN (NC*NCOMP)
#define EC 400000
#define EE (EC*NCOMP)
#define HD 96
#define NB 4096
#define SCAN_BLK 1024
#define NPART ((NN + SCAN_BLK - 1)/SCAN_BLK)

// ---------------- device scratch (static, no runtime allocation) ----------
__device__ __align__(16) float g_h[(size_t)NN*HD];   // ping buffer (h0, even-layer in)
__device__ __align__(16) float g_s[(size_t)NN*HD];   // pong buffer
__device__ int   g_deg[NN];
__device__ int   g_fill[NN];
__device__ int   g_off[NN+1];
__device__ int   g_esrc[EE];
__device__ int   g_part[SCAN_BLK];
// W prepacked, zero-blocks elided, 16B-half XOR swizzle pre-applied:
// [cl(18)][p(2)][chunk(12)][plane(2)][row 144][8 words]
__device__ __align__(16) unsigned g_Wp[(size_t)18*55296];
__device__ __align__(16) float g_bias[18*384];   // [cl][ brz(192) | bin(96) | bnh(96) ]
__device__ __align__(16) float g_pool[NCOMP*NB*HD];
__device__ __align__(16) float g_feat[(size_t)NB*384];
__device__ __align__(16) float g_t1[(size_t)NB*1536];
__device__ __align__(16) float g_t2[(size_t)NB*384];

// ---------------- helpers ---------------------------------------------------
__device__ __forceinline__ unsigned f2bf(float x){
    unsigned u = __float_as_uint(x);
    return (u + 0x7fffu + ((u >> 16) & 1u)) >> 16;   // RN-even
}
__device__ __forceinline__ float bfv(unsigned bits16){ return __uint_as_float(bits16 << 16); }
__device__ __forceinline__ float bflo(unsigned w){ return __uint_as_float(w << 16); }
__device__ __forceinline__ float bfhi(unsigned w){ return __uint_as_float(w & 0xffff0000u); }
__device__ __forceinline__ void pack2(float x, float y, unsigned &hi, unsigned &lo){
    unsigned hx = f2bf(x), hy = f2bf(y);
    hi = hx | (hy << 16);
    lo = f2bf(x - bfv(hx)) | (f2bf(y - bfv(hy)) << 16);
}
__device__ __forceinline__ float ex2f(float x){ float y; asm("ex2.approx.f32 %0, %1;" : "=f"(y) : "f"(x)); return y; }
__device__ __forceinline__ float rcpf(float x){ float y; asm("rcp.approx.f32 %0, %1;" : "=f"(y) : "f"(x)); return y; }
#define L2E 1.4426950408889634f

__device__ __forceinline__ uint32_t smem_u32(const void* p){
    uint32_t a;
    asm("{ .reg .u64 t; cvta.to.shared.u64 t, %1; cvt.u32.u64 %0, t; }" : "=r"(a) : "l"(p));
    return a;
}
__device__ __forceinline__ void mma16816(float* d, const unsigned* a, unsigned b0, unsigned b1){
    asm volatile(
        "mma.sync.aligned.m16n8k16.row.col.f32.bf16.bf16.f32 "
        "{%0,%1,%2,%3}, {%4,%5,%6,%7}, {%8,%9}, {%0,%1,%2,%3};"
        : "+f"(d[0]), "+f"(d[1]), "+f"(d[2]), "+f"(d[3])
        : "r"(a[0]), "r"(a[1]), "r"(a[2]), "r"(a[3]), "r"(b0), "r"(b1));
}
#define LDSM_X4(r0,r1,r2,r3,addr) \
    asm volatile("ldmatrix.sync.aligned.m8n8.x4.shared.b16 {%0,%1,%2,%3}, [%4];" \
        : "=r"(r0), "=r"(r1), "=r"(r2), "=r"(r3) : "r"(addr))
#define LDSM_X2(r0,r1,addr) \
    asm volatile("ldmatrix.sync.aligned.m8n8.x2.shared.b16 {%0,%1}, [%2];" \
        : "=r"(r0), "=r"(r1) : "r"(addr))
#define CP_ASYNC16(sa, ga) \
    asm volatile("cp.async.cg.shared.global [%0], [%1], 16;" :: "r"(sa), "l"(ga))
#define CP_COMMIT() asm volatile("cp.async.commit_group;" ::: "memory")
#define CP_WAITG(n) asm volatile("cp.async.wait_group %0;" :: "n"(n) : "memory")

// f32x2 packed FMA (FFMA2)
__device__ __forceinline__ unsigned long long dup2(float x){
    unsigned u = __float_as_uint(x);
    unsigned long long r;
    asm("mov.b64 %0, {%1, %1};" : "=l"(r) : "r"(u));
    return r;
}
__device__ __forceinline__ unsigned long long ffma2(unsigned long long a,
                                                    unsigned long long b,
                                                    unsigned long long c){
    unsigned long long d;
    asm("fma.rn.f32x2 %0, %1, %2, %3;" : "=l"(d) : "l"(a), "l"(b), "l"(c));
    return d;
}
__device__ __forceinline__ float2 unpk2(unsigned long long v){
    unsigned lo, hi;
    asm("mov.b64 {%0, %1}, %2;" : "=r"(lo), "=r"(hi) : "l"(v));
    float2 f; f.x = __uint_as_float(lo); f.y = __uint_as_float(hi); return f;
}

// swizzled byte offset of (row, 16B-half h) within a W plane
__device__ __forceinline__ uint32_t swzoff(int r, int h){
    return (uint32_t)(r*32 + ((h ^ ((r >> 2) & 1)) << 4));
}

// logical Wpack[k][j]
__device__ float wval(const float* __restrict__ W, const float* __restrict__ wih,
                      const float* __restrict__ whh, int l, int k, int j){
    if (k < 96){
        const float* wr = W + (size_t)(l*96 + k)*96;
        const float* ir = wih + (size_t)j*96;
        float s = 0.f;
        #pragma unroll 8
        for (int t = 0; t < 96; t++) s += wr[t]*ir[t];
        return s;
    }
    int t = k - 96;
    if (j < 192) return whh[(size_t)j*96 + t];
    return whh[(size_t)(j-96)*96 + t];
}

// ---------------- mega kernel: init h0 + counters + pack W + pack bias ------
#define MEGA_IB 225000      // (NN*HD)/256
#define MEGA_PB 3888        // 18*55296/256
#define MEGA_BB 27
__global__ void k_mega(
    const float* __restrict__ x1, const float* __restrict__ x2, const float* __restrict__ x3,
    const float* __restrict__ W1, const float* __restrict__ wih1, const float* __restrict__ whh1,
    const float* __restrict__ W2, const float* __restrict__ wih2, const float* __restrict__ whh2,
    const float* __restrict__ W3, const float* __restrict__ wih3, const float* __restrict__ whh3,
    const float* __restrict__ bih1, const float* __restrict__ bhh1,
    const float* __restrict__ bih2, const float* __restrict__ bhh2,
    const float* __restrict__ bih3, const float* __restrict__ bhh3)
{
    int bid = blockIdx.x;
    int tid = threadIdx.x;
    if (bid < MEGA_IB){
        long long idx = (long long)bid*256 + tid;
        int n = (int)(idx / HD);
        int j = (int)(idx - (long long)n*HD);
        int c = n / NC;
        int ln = n - c*NC;
        const float* x = (c==0)?x1:((c==1)?x2:x3);
        g_h[idx] = (j < 32) ? x[(size_t)ln*32 + j] : 0.f;
        if (idx < NN){ g_deg[(int)idx] = 0; g_fill[(int)idx] = 0; }
    } else if (bid < MEGA_IB + MEGA_PB){
        int gid = (bid - MEGA_IB)*256 + tid;      // < 18*55296
        int cl = gid / 55296;
        int r  = gid - cl*55296;
        int p  = r / 27648;
        int r2 = r - p*27648;
        int chunk = r2 / 2304;
        int r3 = r2 - chunk*2304;
        int plane = r3 / 1152;
        int w  = r3 - plane*1152;
        int row = w >> 3, wk = w & 7;
        int c = cl / 6, l = cl % 6;
        const float* W   = (c==0)?W1:((c==1)?W2:W3);
        const float* wih = (c==0)?wih1:((c==1)?wih2:wih3);
        const float* whh = (c==0)?whh1:((c==1)?whh2:whh3);
        int gi = row / 48, rloc = row - gi*48;
        int nbase = (gi == 0) ? 0 : (gi == 1) ? 96 : ((chunk < 6) ? 192 : 288);
        int n = nbase + p*48 + rloc;
        int khalf = (wk >> 2) ^ ((row >> 2) & 1);
        int k = chunk*16 + (khalf*4 + (wk & 3))*2;
        float v0 = wval(W, wih, whh, l, k, n);
        float v1 = wval(W, wih, whh, l, k+1, n);
        unsigned hi, lo;
        pack2(v0, v1, hi, lo);
        g_Wp[(size_t)gid] = plane ? lo : hi;
    } else {
        int id = (bid - MEGA_IB - MEGA_PB)*256 + tid;
        if (id < 18*384){
            int cl = id / 384;
            int j = id - cl*384;
            int c = cl / 6;
            const float* bih = (c==0)?bih1:((c==1)?bih2:bih3);
            const float* bhh = (c==0)?bhh1:((c==1)?bhh2:bhh3);
            float v;
            if (j < 192)      v = bih[j] + bhh[j];
            else if (j < 288) v = bih[192 + (j-192)];
            else              v = bhh[192 + (j-288)];
            g_bias[cl*384 + j] = v;
        }
    }
}

// ---------------- CSR build -------------------------------------------------
__global__ void k_deg(const int* __restrict__ e1, const int* __restrict__ e2,
                      const int* __restrict__ e3){
    int e = blockIdx.x*blockDim.x + threadIdx.x;
    if (e >= EE) return;
    int c = e / EC, le = e - c*EC;
    const int* ei = (c==0)?e1:((c==1)?e2:e3);
    atomicAdd(&g_deg[c*NC + ei[EC + le]], 1);
}

__global__ void k_scan1(){
    __shared__ int sm[SCAN_BLK];
    int tid = threadIdx.x;
    int i = blockIdx.x*SCAN_BLK + tid;
    int v = (i < NN) ? g_deg[i] : 0;
    sm[tid] = v;
    __syncthreads();
    for (int off = 1; off < SCAN_BLK; off <<= 1){
        int t = 0;
        if (tid >= off) t = sm[tid - off];
        __syncthreads();
        sm[tid] += t;
        __syncthreads();
    }
    if (i < NN) g_off[i] = sm[tid] - v;
    if (tid == SCAN_BLK-1) g_part[blockIdx.x] = sm[tid];
}

__global__ void k_scan2(){
    __shared__ int sm[SCAN_BLK];
    int tid = threadIdx.x;
    int v = (tid < NPART) ? g_part[tid] : 0;
    sm[tid] = v;
    __syncthreads();
    for (int off = 1; off < SCAN_BLK; off <<= 1){
        int t = 0;
        if (tid >= off) t = sm[tid - off];
        __syncthreads();
        sm[tid] += t;
        __syncthreads();
    }
    if (tid < NPART) g_part[tid] = sm[tid] - v;
}

__global__ void k_fill(const int* __restrict__ e1, const int* __restrict__ e2,
                       const int* __restrict__ e3){
    int e = blockIdx.x*blockDim.x + threadIdx.x;
    if (e >= EE) return;
    int c = e / EC, le = e - c*EC;
    const int* ei = (c==0)?e1:((c==1)?e2:e3);
    int dst = ei[EC + le];
    int src = ei[le];
    int dg = c*NC + dst;
    int p = g_off[dg] + g_part[dg >> 10] + atomicAdd(&g_fill[dg], 1);
    g_esrc[p] = c*NC + src;
}

// ---------------- fused GRU layer: gather + mma.sync(ldmatrix) + gates -------
// 64 rows/block, 256 threads (8 warps = 4M x 2N), 2 CTAs/SM.
// W: two 3-chunk (27648 B) cp.async buffers, ping-pong, fills overlapped.
// gru_chunk: ALL 12 LDSM issued up front (A hi/lo + both B planes in
// separate register arrays), then 27 MMAs — max load/compute separation.
#define BIAS_OFF 0            // 1536 B
#define A_HI_OFF 1536         // 64 rows x 400 B = 25600
#define A_LO_OFF 27136
#define W_OFF    52736        // 2 bufs x 27648 B
#define W_BUF    27648
#define SMEM_GRU_TOTAL 108032

__device__ __forceinline__ void fill3(uint32_t smW, const unsigned* gsrc, int tid){
    #pragma unroll
    for (int q = 0; q < 7; q++){
        int idx = tid + 256*q;
        if (idx < 1728){
            CP_ASYNC16(smW + idx*16, (const void*)(gsrc + idx*4));
        }
    }
    CP_COMMIT();
}

template<int G2>
__device__ __forceinline__ void gru_chunk(uint32_t wchunk, uint32_t a_h, uint32_t a_l,
                                          int kglob, uint32_t b4off, uint32_t bt2off,
                                          uint32_t bx2off, float (&acc)[4][3][4]){
    unsigned afh[4], afl[4];
    unsigned b0[3][6], b1[3][6];
    // ---- issue ALL loads first (12 independent LDSM) ----
    LDSM_X4(afh[0], afh[1], afh[2], afh[3], a_h + kglob*32);
    LDSM_X4(afl[0], afl[1], afl[2], afl[3], a_l + kglob*32);
    {
        uint32_t pb = wchunk;
        LDSM_X4(b0[0][0], b0[0][1], b0[0][2], b0[0][3], pb + b4off);
        LDSM_X4(b0[1][0], b0[1][1], b0[1][2], b0[1][3], pb + 1536 + b4off);
        LDSM_X4(b0[2][0], b0[2][1], b0[2][2], b0[2][3], pb + 3072 + b4off);
        LDSM_X4(b0[0][4], b0[0][5], b0[1][4], b0[1][5], pb + bt2off);
        LDSM_X2(b0[2][4], b0[2][5], pb + bx2off);
    }
    {
        uint32_t pb = wchunk + 4608;
        LDSM_X4(b1[0][0], b1[0][1], b1[0][2], b1[0][3], pb + b4off);
        LDSM_X4(b1[1][0], b1[1][1], b1[1][2], b1[1][3], pb + 1536 + b4off);
        LDSM_X4(b1[2][0], b1[2][1], b1[2][2], b1[2][3], pb + 3072 + b4off);
        LDSM_X4(b1[0][4], b1[0][5], b1[1][4], b1[1][5], pb + bt2off);
        LDSM_X2(b1[2][4], b1[2][5], pb + bx2off);
    }
    // ---- then all 27 MMAs ----
    #pragma unroll
    for (int gi = 0; gi < 3; gi++){
        const int ga = (gi < 2) ? gi : G2;
        #pragma unroll
        for (int t = 0; t < 3; t++){
            mma16816(acc[ga][t], afh, b0[gi][2*t], b0[gi][2*t+1]);
            mma16816(acc[ga][t], afl, b0[gi][2*t], b0[gi][2*t+1]);
            mma16816(acc[ga][t], afh, b1[gi][2*t], b1[gi][2*t+1]);
        }
    }
}

template<int G2>
__device__ __forceinline__ void compute3(uint32_t wbuf, uint32_t a_h, uint32_t a_l,
                                         int kbase, uint32_t b4off, uint32_t bt2off,
                                         uint32_t bx2off, float (&acc)[4][3][4]){
    #pragma unroll
    for (int c = 0; c < 3; c++)
        gru_chunk<G2>(wbuf + c*9216, a_h, a_l, kbase + c, b4off, bt2off, bx2off, acc);
}

__device__ __forceinline__ void gru_epilogue(
    int p, float (&acc)[4][3][4], const float* sb,
    const unsigned* Ahw, const unsigned* Alw, float* hout,
    int comp, int row0, int wm, int wn, int lr, int lq)
{
    #pragma unroll
    for (int t = 0; t < 3; t++){
        int f0 = p*48 + wn*24 + t*8 + 2*lq;
        float bR0 = sb[f0],       bR1 = sb[f0+1];
        float bZ0 = sb[96+f0],    bZ1 = sb[96+f0+1];
        float bI0 = sb[192+f0],   bI1 = sb[192+f0+1];
        float bN0 = sb[288+f0],   bN1 = sb[288+f0+1];
        #pragma unroll
        for (int half = 0; half < 2; half++){
            int row = wm*16 + lr + half*8;
            size_t base = (size_t)(comp*NC + row0 + row)*96;
            int wofs = row*100 + 48 + (f0 >> 1);
            unsigned hw = Ahw[wofs], lw = Alw[wofs];
            float hx = bflo(hw) + bflo(lw);
            float hy = bfhi(hw) + bfhi(lw);
            int ci = half*2;
            float xr0 = fminf(fmaxf((acc[0][t][ci]   + bR0)*L2E, -30.f), 30.f);
            float xr1 = fminf(fmaxf((acc[0][t][ci+1] + bR1)*L2E, -30.f), 30.f);
            float xz0 = fminf(fmaxf((acc[1][t][ci]   + bZ0)*L2E, -30.f), 30.f);
            float xz1 = fminf(fmaxf((acc[1][t][ci+1] + bZ1)*L2E, -30.f), 30.f);
            float er0 = ex2f(xr0), er1 = ex2f(xr1);
            float ez0 = ex2f(xz0), ez1 = ex2f(xz1);
            float d1 = er0 + 1.f, d2 = ez0 + 1.f, d3 = er1 + 1.f, d4 = ez1 + 1.f;
            float p12 = d1*d2, p34 = d3*d4;
            float rp = rcpf(p12*p34);
            float q12 = rp*p34, q34 = rp*p12;
            float rr0 = er0*(q12*d2), zz0 = ez0*(q12*d1);
            float rr1 = er1*(q34*d4), zz1 = ez1*(q34*d3);
            float t0 = fmaf(rr0, acc[3][t][ci]   + bN0, acc[2][t][ci]   + bI0);
            float t1 = fmaf(rr1, acc[3][t][ci+1] + bN1, acc[2][t][ci+1] + bI1);
            float lt0 = fminf(fmaxf(t0*(2.f*L2E), -30.f), 30.f);
            float lt1 = fminf(fmaxf(t1*(2.f*L2E), -30.f), 30.f);
            float e0 = ex2f(lt0), e1 = ex2f(lt1);
            float dt0 = e0 + 1.f, dt1 = e1 + 1.f;
            float rpt = rcpf(dt0*dt1);
            float nn0 = fmaf(-2.f, rpt*dt1, 1.f);
            float nn1 = fmaf(-2.f, rpt*dt0, 1.f);
            float o0 = fmaf(zz0, hx - nn0, nn0);
            float o1 = fmaf(zz1, hy - nn1, nn1);
            *(float2*)(hout + base + f0) = make_float2(o0, o1);
        }
    }
}

template<int WARM>
__global__ void __launch_bounds__(256, 2) k_gru(int layer){
    extern __shared__ char smc[];
    const uint32_t smb = smem_u32(smc);
    float* sb = (float*)(smc + BIAS_OFF);

    const int comp = blockIdx.y;
    const int cl = comp*6 + layer;
    const int row0 = blockIdx.x*64;
    const int tid = threadIdx.x;
    const int lane = tid & 31;
    const int wid = tid >> 5;
    const int wm = wid & 3;          // rows wm*16..+15
    const int wn = wid >> 2;         // 0..1
    const int lr = lane >> 2;        // 0..7
    const int lq = lane & 3;         // 0..3

    const unsigned* wsrc = g_Wp + (size_t)cl*55296;
    const uint32_t w0 = smb + W_OFF;
    const uint32_t w1 = w0 + W_BUF;

    // kick off W fills (overlap the gather)
    fill3(w0, wsrc, tid);
    fill3(w1, wsrc + 3*2304, tid);

    for (int i = tid; i < 384; i += 256) sb[i] = g_bias[cl*384 + i];

    const float* hin  = WARM ? g_h : ((layer & 1) ? g_s : g_h);
    float*       hout = WARM ? g_s : ((layer & 1) ? g_h : g_s);

    // ---- wave-parallel gather + stage A (bf16 hi/lo, 100-word stride) ----
    {
        unsigned* Ahw2 = (unsigned*)(smc + A_HI_OFF);
        unsigned* Alw2 = (unsigned*)(smc + A_LO_OFF);
        const int nd = comp*NC + row0 + wid*8;
        float2 s0[8], s1[8];
        #pragma unroll
        for (int r = 0; r < 8; r++){ s0[r] = make_float2(0.f,0.f); s1[r] = make_float2(0.f,0.f); }
        if (!WARM){
            int beg[8], end8[8];
            #pragma unroll
            for (int r = 0; r < 8; r++){
                int node = nd + r;
                beg[r] = __ldg(&g_off[node]) + __ldg(&g_part[node >> 10]);
            }
            #pragma unroll
            for (int r = 0; r < 8; r++){
                int n1 = nd + r + 1;
                end8[r] = (n1 == NN) ? EE : (__ldg(&g_off[n1]) + __ldg(&g_part[n1 >> 10]));
            }
            int md = 0;
            #pragma unroll
            for (int r = 0; r < 8; r++) md = max(md, end8[r] - beg[r]);
            for (int j = 0; j < md; j++){
                int sidx[8];
                #pragma unroll
                for (int r = 0; r < 8; r++)
                    sidx[r] = (j < end8[r] - beg[r]) ? __ldg(&g_esrc[beg[r] + j]) : -1;
                #pragma unroll
                for (int r = 0; r < 8; r++){
                    if (sidx[r] >= 0){
                        const float2* hp = (const float2*)(hin + (size_t)sidx[r]*96);
                        float2 v = __ldg(hp + lane);
                        s0[r].x += v.x; s0[r].y += v.y;
                        if (lane < 16){
                            float2 v1 = __ldg(hp + 32 + lane);
                            s1[r].x += v1.x; s1[r].y += v1.y;
                        }
                    }
                }
            }
        }
        // batch h-row loads (all independent)
        float2 h0v[8], h1v[8];
        #pragma unroll
        for (int r = 0; r < 8; r++){
            const float2* hr = (const float2*)(hin + (size_t)(nd + r)*96);
            h0v[r] = __ldg(hr + lane);
            if (lane < 16) h1v[r] = __ldg(hr + 32 + lane);
        }
        #pragma unroll
        for (int r = 0; r < 8; r++){
            int row = wid*8 + r;
            int wb = row*100;
            unsigned hi, lo;
            pack2(s0[r].x, s0[r].y, hi, lo);
            Ahw2[wb + lane] = hi;  Alw2[wb + lane] = lo;
            pack2(h0v[r].x, h0v[r].y, hi, lo);
            Ahw2[wb + 48 + lane] = hi;  Alw2[wb + 48 + lane] = lo;
            if (lane < 16){
                pack2(s1[r].x, s1[r].y, hi, lo);
                Ahw2[wb + 32 + lane] = hi;  Alw2[wb + 32 + lane] = lo;
                pack2(h1v[r].x, h1v[r].y, hi, lo);
                Ahw2[wb + 80 + lane] = hi;  Alw2[wb + 80 + lane] = lo;
            }
        }
    }

    // per-warp ldmatrix addresses
    const uint32_t a_h = smb + A_HI_OFF +
        ((wm*16 + (lane & 15))*100 + ((lane >> 4) << 2))*4;
    const uint32_t a_l = a_h + (A_LO_OFF - A_HI_OFF);
    const int hsel = (lane >> 3) & 1;
    const uint32_t b4off  = wn*768 + swzoff(((lane >> 4) << 3) + (lane & 7), hsel);
    const uint32_t bt2off = (lane >> 4)*1536 + wn*768 + swzoff(16 + (lane & 7), hsel);
    const uint32_t bx2off = 3072 + wn*768 + swzoff(16 + (lane & 7), hsel);

    const unsigned* Ahw = (const unsigned*)(smc + A_HI_OFF);
    const unsigned* Alw = (const unsigned*)(smc + A_LO_OFF);

    // boundary: all-done-X barrier, refill X, ensure Y ready+visible
    #define BOUNDARY(bufaddr, srcoff) do { \
        __syncthreads(); \
        fill3(bufaddr, wsrc + (srcoff)*2304, tid); \
        CP_WAITG(1); \
        __syncthreads(); \
    } while(0)

    float acc[4][3][4];
    #pragma unroll
    for (int g = 0; g < 4; g++)
        #pragma unroll
        for (int t = 0; t < 3; t++)
            #pragma unroll
            for (int i = 0; i < 4; i++) acc[g][t][i] = 0.f;

    CP_WAITG(1);
    __syncthreads();   // A staged + W0 ready

    compute3<2>(w0, a_h, a_l, 0, b4off, bt2off, bx2off, acc);
    BOUNDARY(w0, 6);
    compute3<2>(w1, a_h, a_l, 3, b4off, bt2off, bx2off, acc);
    BOUNDARY(w1, 9);
    compute3<3>(w0, a_h, a_l, 6, b4off, bt2off, bx2off, acc);
    BOUNDARY(w0, 12);
    compute3<3>(w1, a_h, a_l, 9, b4off, bt2off, bx2off, acc);
    BOUNDARY(w1, 15);
    gru_epilogue(0, acc, sb, Ahw, Alw, hout, comp, row0, wm, wn, lr, lq);

    #pragma unroll
    for (int g = 0; g < 4; g++)
        #pragma unroll
        for (int t = 0; t < 3; t++)
            #pragma unroll
            for (int i = 0; i < 4; i++) acc[g][t][i] = 0.f;

    compute3<2>(w0, a_h, a_l, 0, b4off, bt2off, bx2off, acc);
    BOUNDARY(w0, 18);
    compute3<2>(w1, a_h, a_l, 3, b4off, bt2off, bx2off, acc);
    BOUNDARY(w1, 21);
    compute3<3>(w0, a_h, a_l, 6, b4off, bt2off, bx2off, acc);
    __syncthreads();
    CP_WAITG(0);
    __syncthreads();
    compute3<3>(w1, a_h, a_l, 9, b4off, bt2off, bx2off, acc);
    gru_epilogue(1, acc, sb, Ahw, Alw, hout, comp, row0, wm, wn, lr, lq);
    #undef BOUNDARY
}

// ---------------- pooling: mean of relu(h) over sorted batch ranges ---------
__global__ void k_pool(const int* __restrict__ b1, const int* __restrict__ b2,
                       const int* __restrict__ b3){
    int b = blockIdx.x;
    int c = blockIdx.y;
    const int* batch = (c==0)?b1:((c==1)?b2:b3);
    int lo = 0, hi = NC;
    while (lo < hi){ int m = (lo+hi) >> 1; if (batch[m] < b) lo = m+1; else hi = m; }
    int s0 = lo;
    hi = NC;
    while (lo < hi){ int m = (lo+hi) >> 1; if (batch[m] < b+1) lo = m+1; else hi = m; }
    int e0 = lo;
    float denom = fmaxf((float)(e0 - s0), 1.f);
    int f = threadIdx.x;
    float sum = 0.f;
    for (int n = s0; n < e0; n++)
        sum += fmaxf(g_h[(size_t)(c*NC + n)*HD + f], 0.f);
    g_pool[((size_t)c*NB + b)*HD + f] = sum / denom;
}

// ---------------- feature assembly ------------------------------------------
__global__ void k_feat(){
    int idx = blockIdx.x*blockDim.x + threadIdx.x;
    if (idx >= NB*384) return;
    int b = idx / 384;
    int j = idx - b*384;
    float v;
    if (j < 96)       v = g_pool[(size_t)b*HD + j];
    else if (j < 192) v = g_pool[((size_t)NB + b)*HD + (j-96)];
    else if (j < 288) v = g_pool[((size_t)2*NB + b)*HD + (j-192)];
    else {
        int jj = j - 288;
        v = g_pool[(size_t)b*HD + jj]
          * g_pool[((size_t)NB + b)*HD + jj]
          * g_pool[((size_t)2*NB + b)*HD + jj];
    }
    g_feat[idx] = v;
}

// ---------------- MLP GEMM (f32x2 FFMA2, globals resolved in device code) ---
template<int MODE>
__global__ void __launch_bounds__(256) k_gemm(const float* __restrict__ B,
                                              const float* __restrict__ bias){
    const float* A = (MODE == 0) ? g_feat : g_t1;
    float*       C = (MODE == 0) ? g_t1   : g_t2;
    const int N = (MODE == 0) ? 1536 : 384;
    const int K = (MODE == 0) ? 384  : 1536;

    __shared__ float As[64*33];
    __shared__ __align__(16) float Bs[32*68];
    int txx = threadIdx.x & 15;
    int tyy = threadIdx.x >> 4;
    int m0 = blockIdx.y*64;
    int n0 = blockIdx.x*64;
    unsigned long long acc2[4][2];
    #pragma unroll
    for (int i = 0; i < 4; i++){ acc2[i][0] = 0ull; acc2[i][1] = 0ull; }

    for (int kc = 0; kc < K; kc += 32){
        __syncthreads();
        for (int i = threadIdx.x; i < 64*32; i += 256){
            int r = i >> 5, k = i & 31;
            As[r*33 + k] = A[(size_t)(m0 + r)*K + kc + k];
        }
        for (int i = threadIdx.x; i < 32*64; i += 256){
            int k = i >> 6, cc = i & 63;
            Bs[k*68 + cc] = B[(size_t)(kc + k)*N + n0 + cc];
        }
        __syncthreads();
        #pragma unroll 8
        for (int k = 0; k < 32; k++){
            unsigned long long b0 = *(const unsigned long long*)&Bs[k*68 + txx*4];
            unsigned long long b1 = *(const unsigned long long*)&Bs[k*68 + txx*4 + 2];
            #pragma unroll
            for (int i = 0; i < 4; i++){
                unsigned long long ai = dup2(As[(tyy*4 + i)*33 + k]);
                acc2[i][0] = ffma2(ai, b0, acc2[i][0]);
                acc2[i][1] = ffma2(ai, b1, acc2[i][1]);
            }
        }
    }
    #pragma unroll
    for (int i = 0; i < 4; i++){
        int row = m0 + tyy*4 + i;
        #pragma unroll
        for (int j2 = 0; j2 < 2; j2++){
            float2 v = unpk2(acc2[i][j2]);
            int col = n0 + txx*4 + j2*2;
            C[(size_t)row*N + col]     = fmaxf(v.x + bias[col], 0.f);
            C[(size_t)row*N + col + 1] = fmaxf(v.y + bias[col+1], 0.f);
        }
    }
}

// ---------------- fc3: [4096,384] @ [384,3] ---------------------------------
__global__ void k_fc3(const float* __restrict__ w, const float* __restrict__ b,
                      float* __restrict__ out){
    int gt = blockIdx.x*blockDim.x + threadIdx.x;
    int row = gt >> 5;
    int lane = gt & 31;
    if (row >= NB) return;
    float a0 = 0.f, a1 = 0.f, a2 = 0.f;
    for (int k = lane; k < 384; k += 32){
        float f = g_t2[(size_t)row*384 + k];
        a0 += f*w[k*3 + 0];
        a1 += f*w[k*3 + 1];
        a2 += f*w[k*3 + 2];
    }
    #pragma unroll
    for (int o = 16; o; o >>= 1){
        a0 += __shfl_down_sync(0xffffffffu, a0, o);
        a1 += __shfl_down_sync(0xffffffffu, a1, o);
        a2 += __shfl_down_sync(0xffffffffu, a2, o);
    }
    if (lane == 0){
        out[row*3 + 0] = a0 + b[0];
        out[row*3 + 1] = a1 + b[1];
        out[row*3 + 2] = a2 + b[2];
    }
}

// ---------------- launch ----------------------------------------------------
extern "C" void kernel_launch(void* const* d_in, const int* in_sizes, int n_in,
                              void* d_out, int out_size) {
    const float* xs[3]   = {0,0,0};
    const int*   es[3]   = {0,0,0};
    const int*   bs[3]   = {0,0,0};
    const float* Ws[3]   = {0,0,0};
    const float* wihs[3] = {0,0,0};
    const float* whhs[3] = {0,0,0};
    const float* bihs[3] = {0,0,0};
    const float* bhhs[3] = {0,0,0};
    const float* fcw[2]  = {0,0};
    const float* fc1b = 0; const float* fc2b = 0;
    const float* fc3w = 0; const float* fc3b = 0;
    int nx=0, ne=0, nb=0, nW=0, nwpair=0, nbpair=0, nfcw=0;
    for (int i = 0; i < n_in; i++){
        int s = in_sizes[i];
        const void* p = d_in[i];
        switch (s){
            case 6400000: if (nx < 3) xs[nx++] = (const float*)p; break;
            case 800000:  if (ne < 3) es[ne++] = (const int*)p;   break;
            case 200000:  if (nb < 3) bs[nb++] = (const int*)p;   break;
            case 55296:   if (nW < 3) Ws[nW++] = (const float*)p; break;
            case 27648:   { int c = nwpair/2;
                            if (c < 3){ if ((nwpair & 1) == 0) wihs[c] = (const float*)p;
                                        else                   whhs[c] = (const float*)p; }
                            nwpair++; } break;
            case 288:     { int c = nbpair/2;
                            if (c < 3){ if ((nbpair & 1) == 0) bihs[c] = (const float*)p;
                                        else                   bhhs[c] = (const float*)p; }
                            nbpair++; } break;
            case 589824:  if (nfcw < 2) fcw[nfcw++] = (const float*)p; break;
            case 1536:    fc1b = (const float*)p; break;
            case 384:     fc2b = (const float*)p; break;
            case 1152:    fc3w = (const float*)p; break;
            case 3:       fc3b = (const float*)p; break;
            default: break;
        }
    }
    const float* fc1w = fcw[0];
    const float* fc2w = fcw[1];
    float* out = (float*)d_out;

    cudaFuncSetAttribute(k_gru<0>, cudaFuncAttributeMaxDynamicSharedMemorySize, SMEM_GRU_TOTAL);
    cudaFuncSetAttribute(k_gru<1>, cudaFuncAttributeMaxDynamicSharedMemorySize, SMEM_GRU_TOTAL);

    // 1: mega init (h0 + counters + W prepack + bias pack)
    k_mega<<<MEGA_IB + MEGA_PB + MEGA_BB, 256>>>(
        xs[0], xs[1], xs[2],
        Ws[0], wihs[0], whhs[0], Ws[1], wihs[1], whhs[1], Ws[2], wihs[2], whhs[2],
        bihs[0], bhhs[0], bihs[1], bhhs[1], bihs[2], bhhs[2]);
    // 2-3: CSR histogram + block scan
    k_deg<<<(EE + 255)/256, 256>>>(es[0], es[1], es[2]);
    k_scan1<<<NPART, SCAN_BLK>>>();
    // 4: telemetry warmup GRU (no gather; writes g_s, overwritten by layer 0)
    k_gru<1><<<dim3(200, 3), 256, SMEM_GRU_TOTAL>>>(0);
    // 5-6: finish CSR
    k_scan2<<<1, SCAN_BLK>>>();
    k_fill<<<(EE + 255)/256, 256>>>(es[0], es[1], es[2]);

    const int gruBlocks = NC/64;   // 3125
    for (int l = 0; l < 6; l++)
        k_gru<0><<<dim3(gruBlocks, 3), 256, SMEM_GRU_TOTAL>>>(l);

    k_pool<<<dim3(NB, 3), 96>>>(bs[0], bs[1], bs[2]);
    k_feat<<<(NB*384 + 255)/256, 256>>>();
    k_gemm<0><<<dim3(1536/64, NB/64), 256>>>(fc1w, fc1b);
    k_gemm<1><<<dim3(384/64,  NB/64), 256>>>(fc2w, fc2b);
    k_fc3<<<(NB*32 + 255)/256, 256>>>(fc3w, fc3b, out);
}

// round 16
// speedup vs baseline: 1.2572x; 1.2572x over previous
#include <cuda_runtime.h>
#include <cstdint>

#define NC 200000
#define NCOMP 3
#define NN (NC*NCOMP)
#define EC 400000
#define EE (EC*NCOMP)
#define HD 96
#define NB 4096
#define SCAN_BLK 1024
#define NPART ((NN + SCAN_BLK - 1)/SCAN_BLK)

// ---------------- device scratch (static, no runtime allocation) ----------
__device__ __align__(16) float g_h[(size_t)NN*HD];   // ping buffer (h0, even-layer in)
__device__ __align__(16) float g_s[(size_t)NN*HD];   // pong buffer
__device__ int   g_deg[NN];
__device__ int   g_fill[NN];
__device__ int   g_off[NN+1];
__device__ int   g_esrc[EE];
__device__ int   g_part[SCAN_BLK];
// W prepacked, zero-blocks elided, 16B-half XOR swizzle pre-applied:
// [cl(18)][p(2)][chunk(12)][plane(2)][row 144][8 words]
__device__ __align__(16) unsigned g_Wp[(size_t)18*55296];
__device__ __align__(16) float g_bias[18*384];   // [cl][ brz(192) | bin(96) | bnh(96) ]
__device__ __align__(16) float g_pool[NCOMP*NB*HD];
__device__ __align__(16) float g_feat[(size_t)NB*384];
__device__ __align__(16) float g_t1[(size_t)NB*1536];
__device__ __align__(16) float g_t2[(size_t)NB*384];

// ---------------- helpers ---------------------------------------------------
__device__ __forceinline__ unsigned f2bf(float x){
    unsigned u = __float_as_uint(x);
    return (u + 0x7fffu + ((u >> 16) & 1u)) >> 16;   // RN-even
}
__device__ __forceinline__ float bfv(unsigned bits16){ return __uint_as_float(bits16 << 16); }
__device__ __forceinline__ float bflo(unsigned w){ return __uint_as_float(w << 16); }
__device__ __forceinline__ float bfhi(unsigned w){ return __uint_as_float(w & 0xffff0000u); }
__device__ __forceinline__ void pack2(float x, float y, unsigned &hi, unsigned &lo){
    unsigned hx = f2bf(x), hy = f2bf(y);
    hi = hx | (hy << 16);
    lo = f2bf(x - bfv(hx)) | (f2bf(y - bfv(hy)) << 16);
}
__device__ __forceinline__ float ex2f(float x){ float y; asm("ex2.approx.f32 %0, %1;" : "=f"(y) : "f"(x)); return y; }
__device__ __forceinline__ float rcpf(float x){ float y; asm("rcp.approx.f32 %0, %1;" : "=f"(y) : "f"(x)); return y; }
#define L2E 1.4426950408889634f

__device__ __forceinline__ uint32_t smem_u32(const void* p){
    uint32_t a;
    asm("{ .reg .u64 t; cvta.to.shared.u64 t, %1; cvt.u32.u64 %0, t; }" : "=r"(a) : "l"(p));
    return a;
}
__device__ __forceinline__ void mma16816(float* d, const unsigned* a, unsigned b0, unsigned b1){
    asm volatile(
        "mma.sync.aligned.m16n8k16.row.col.f32.bf16.bf16.f32 "
        "{%0,%1,%2,%3}, {%4,%5,%6,%7}, {%8,%9}, {%0,%1,%2,%3};"
        : "+f"(d[0]), "+f"(d[1]), "+f"(d[2]), "+f"(d[3])
        : "r"(a[0]), "r"(a[1]), "r"(a[2]), "r"(a[3]), "r"(b0), "r"(b1));
}
#define LDSM_X4(r0,r1,r2,r3,addr) \
    asm volatile("ldmatrix.sync.aligned.m8n8.x4.shared.b16 {%0,%1,%2,%3}, [%4];" \
        : "=r"(r0), "=r"(r1), "=r"(r2), "=r"(r3) : "r"(addr))
#define LDSM_X2(r0,r1,addr) \
    asm volatile("ldmatrix.sync.aligned.m8n8.x2.shared.b16 {%0,%1}, [%2];" \
        : "=r"(r0), "=r"(r1) : "r"(addr))
#define CP_ASYNC16(sa, ga) \
    asm volatile("cp.async.cg.shared.global [%0], [%1], 16;" :: "r"(sa), "l"(ga))
#define CP_COMMIT() asm volatile("cp.async.commit_group;" ::: "memory")
#define CP_WAITG(n) asm volatile("cp.async.wait_group %0;" :: "n"(n) : "memory")

// f32x2 packed FMA (FFMA2)
__device__ __forceinline__ unsigned long long dup2(float x){
    unsigned u = __float_as_uint(x);
    unsigned long long r;
    asm("mov.b64 %0, {%1, %1};" : "=l"(r) : "r"(u));
    return r;
}
__device__ __forceinline__ unsigned long long ffma2(unsigned long long a,
                                                    unsigned long long b,
                                                    unsigned long long c){
    unsigned long long d;
    asm("fma.rn.f32x2 %0, %1, %2, %3;" : "=l"(d) : "l"(a), "l"(b), "l"(c));
    return d;
}
__device__ __forceinline__ float2 unpk2(unsigned long long v){
    unsigned lo, hi;
    asm("mov.b64 {%0, %1}, %2;" : "=r"(lo), "=r"(hi) : "l"(v));
    float2 f; f.x = __uint_as_float(lo); f.y = __uint_as_float(hi); return f;
}

// swizzled byte offset of (row, 16B-half h) within a W plane
__device__ __forceinline__ uint32_t swzoff(int r, int h){
    return (uint32_t)(r*32 + ((h ^ ((r >> 2) & 1)) << 4));
}

// logical Wpack[k][j]
__device__ float wval(const float* __restrict__ W, const float* __restrict__ wih,
                      const float* __restrict__ whh, int l, int k, int j){
    if (k < 96){
        const float* wr = W + (size_t)(l*96 + k)*96;
        const float* ir = wih + (size_t)j*96;
        float s = 0.f;
        #pragma unroll 8
        for (int t = 0; t < 96; t++) s += wr[t]*ir[t];
        return s;
    }
    int t = k - 96;
    if (j < 192) return whh[(size_t)j*96 + t];
    return whh[(size_t)(j-96)*96 + t];
}

// ---------------- mega kernel: init h0 + counters + pack W + pack bias ------
#define MEGA_IB 225000      // (NN*HD)/256
#define MEGA_PB 3888        // 18*55296/256
#define MEGA_BB 27
__global__ void k_mega(
    const float* __restrict__ x1, const float* __restrict__ x2, const float* __restrict__ x3,
    const float* __restrict__ W1, const float* __restrict__ wih1, const float* __restrict__ whh1,
    const float* __restrict__ W2, const float* __restrict__ wih2, const float* __restrict__ whh2,
    const float* __restrict__ W3, const float* __restrict__ wih3, const float* __restrict__ whh3,
    const float* __restrict__ bih1, const float* __restrict__ bhh1,
    const float* __restrict__ bih2, const float* __restrict__ bhh2,
    const float* __restrict__ bih3, const float* __restrict__ bhh3)
{
    int bid = blockIdx.x;
    int tid = threadIdx.x;
    if (bid < MEGA_IB){
        long long idx = (long long)bid*256 + tid;
        int n = (int)(idx / HD);
        int j = (int)(idx - (long long)n*HD);
        int c = n / NC;
        int ln = n - c*NC;
        const float* x = (c==0)?x1:((c==1)?x2:x3);
        g_h[idx] = (j < 32) ? x[(size_t)ln*32 + j] : 0.f;
        if (idx < NN){ g_deg[(int)idx] = 0; g_fill[(int)idx] = 0; }
    } else if (bid < MEGA_IB + MEGA_PB){
        int gid = (bid - MEGA_IB)*256 + tid;      // < 18*55296
        int cl = gid / 55296;
        int r  = gid - cl*55296;
        int p  = r / 27648;
        int r2 = r - p*27648;
        int chunk = r2 / 2304;
        int r3 = r2 - chunk*2304;
        int plane = r3 / 1152;
        int w  = r3 - plane*1152;
        int row = w >> 3, wk = w & 7;
        int c = cl / 6, l = cl % 6;
        const float* W   = (c==0)?W1:((c==1)?W2:W3);
        const float* wih = (c==0)?wih1:((c==1)?wih2:wih3);
        const float* whh = (c==0)?whh1:((c==1)?whh2:whh3);
        int gi = row / 48, rloc = row - gi*48;
        int nbase = (gi == 0) ? 0 : (gi == 1) ? 96 : ((chunk < 6) ? 192 : 288);
        int n = nbase + p*48 + rloc;
        int khalf = (wk >> 2) ^ ((row >> 2) & 1);
        int k = chunk*16 + (khalf*4 + (wk & 3))*2;
        float v0 = wval(W, wih, whh, l, k, n);
        float v1 = wval(W, wih, whh, l, k+1, n);
        unsigned hi, lo;
        pack2(v0, v1, hi, lo);
        g_Wp[(size_t)gid] = plane ? lo : hi;
    } else {
        int id = (bid - MEGA_IB - MEGA_PB)*256 + tid;
        if (id < 18*384){
            int cl = id / 384;
            int j = id - cl*384;
            int c = cl / 6;
            const float* bih = (c==0)?bih1:((c==1)?bih2:bih3);
            const float* bhh = (c==0)?bhh1:((c==1)?bhh2:bhh3);
            float v;
            if (j < 192)      v = bih[j] + bhh[j];
            else if (j < 288) v = bih[192 + (j-192)];
            else              v = bhh[192 + (j-288)];
            g_bias[cl*384 + j] = v;
        }
    }
}

// ---------------- CSR build -------------------------------------------------
__global__ void k_deg(const int* __restrict__ e1, const int* __restrict__ e2,
                      const int* __restrict__ e3){
    int e = blockIdx.x*blockDim.x + threadIdx.x;
    if (e >= EE) return;
    int c = e / EC, le = e - c*EC;
    const int* ei = (c==0)?e1:((c==1)?e2:e3);
    atomicAdd(&g_deg[c*NC + ei[EC + le]], 1);
}

__global__ void k_scan1(){
    __shared__ int sm[SCAN_BLK];
    int tid = threadIdx.x;
    int i = blockIdx.x*SCAN_BLK + tid;
    int v = (i < NN) ? g_deg[i] : 0;
    sm[tid] = v;
    __syncthreads();
    for (int off = 1; off < SCAN_BLK; off <<= 1){
        int t = 0;
        if (tid >= off) t = sm[tid - off];
        __syncthreads();
        sm[tid] += t;
        __syncthreads();
    }
    if (i < NN) g_off[i] = sm[tid] - v;
    if (tid == SCAN_BLK-1) g_part[blockIdx.x] = sm[tid];
}

__global__ void k_scan2(){
    __shared__ int sm[SCAN_BLK];
    int tid = threadIdx.x;
    int v = (tid < NPART) ? g_part[tid] : 0;
    sm[tid] = v;
    __syncthreads();
    for (int off = 1; off < SCAN_BLK; off <<= 1){
        int t = 0;
        if (tid >= off) t = sm[tid - off];
        __syncthreads();
        sm[tid] += t;
        __syncthreads();
    }
    if (tid < NPART) g_part[tid] = sm[tid] - v;
}

__global__ void k_fill(const int* __restrict__ e1, const int* __restrict__ e2,
                       const int* __restrict__ e3){
    int e = blockIdx.x*blockDim.x + threadIdx.x;
    if (e >= EE) return;
    int c = e / EC, le = e - c*EC;
    const int* ei = (c==0)?e1:((c==1)?e2:e3);
    int dst = ei[EC + le];
    int src = ei[le];
    int dg = c*NC + dst;
    int p = g_off[dg] + g_part[dg >> 10] + atomicAdd(&g_fill[dg], 1);
    g_esrc[p] = c*NC + src;
}

// ---------------- fused GRU layer: gather + mma.sync(ldmatrix) + gates -------
// 64 rows/block, 256 threads (8 warps = 4M x 2N), 2 CTAs/SM.
// W: two 3-chunk (27648 B) cp.async buffers, ping-pong, fills overlapped.
// Gather: wave-parallel, float4 row loads (lanes 0-23), 1 LDG.128/edge.
#define BIAS_OFF 0            // 1536 B
#define A_HI_OFF 1536         // 64 rows x 400 B = 25600
#define A_LO_OFF 27136
#define W_OFF    52736        // 2 bufs x 27648 B
#define W_BUF    27648
#define SMEM_GRU_TOTAL 108032

__device__ __forceinline__ void fill3(uint32_t smW, const unsigned* gsrc, int tid){
    #pragma unroll
    for (int q = 0; q < 7; q++){
        int idx = tid + 256*q;
        if (idx < 1728){
            CP_ASYNC16(smW + idx*16, (const void*)(gsrc + idx*4));
        }
    }
    CP_COMMIT();
}

template<int G2>
__device__ __forceinline__ void gru_chunk(uint32_t wchunk, uint32_t a_h, uint32_t a_l,
                                          int kglob, uint32_t b4off, uint32_t bt2off,
                                          uint32_t bx2off, float (&acc)[4][3][4]){
    unsigned afh[4], afl[4];
    unsigned b0[3][6], b1[3][6];
    // ---- issue ALL loads first (12 independent LDSM) ----
    LDSM_X4(afh[0], afh[1], afh[2], afh[3], a_h + kglob*32);
    LDSM_X4(afl[0], afl[1], afl[2], afl[3], a_l + kglob*32);
    {
        uint32_t pb = wchunk;
        LDSM_X4(b0[0][0], b0[0][1], b0[0][2], b0[0][3], pb + b4off);
        LDSM_X4(b0[1][0], b0[1][1], b0[1][2], b0[1][3], pb + 1536 + b4off);
        LDSM_X4(b0[2][0], b0[2][1], b0[2][2], b0[2][3], pb + 3072 + b4off);
        LDSM_X4(b0[0][4], b0[0][5], b0[1][4], b0[1][5], pb + bt2off);
        LDSM_X2(b0[2][4], b0[2][5], pb + bx2off);
    }
    {
        uint32_t pb = wchunk + 4608;
        LDSM_X4(b1[0][0], b1[0][1], b1[0][2], b1[0][3], pb + b4off);
        LDSM_X4(b1[1][0], b1[1][1], b1[1][2], b1[1][3], pb + 1536 + b4off);
        LDSM_X4(b1[2][0], b1[2][1], b1[2][2], b1[2][3], pb + 3072 + b4off);
        LDSM_X4(b1[0][4], b1[0][5], b1[1][4], b1[1][5], pb + bt2off);
        LDSM_X2(b1[2][4], b1[2][5], pb + bx2off);
    }
    // ---- then all 27 MMAs ----
    #pragma unroll
    for (int gi = 0; gi < 3; gi++){
        const int ga = (gi < 2) ? gi : G2;
        #pragma unroll
        for (int t = 0; t < 3; t++){
            mma16816(acc[ga][t], afh, b0[gi][2*t], b0[gi][2*t+1]);
            mma16816(acc[ga][t], afl, b0[gi][2*t], b0[gi][2*t+1]);
            mma16816(acc[ga][t], afh, b1[gi][2*t], b1[gi][2*t+1]);
        }
    }
}

template<int G2>
__device__ __forceinline__ void compute3(uint32_t wbuf, uint32_t a_h, uint32_t a_l,
                                         int kbase, uint32_t b4off, uint32_t bt2off,
                                         uint32_t bx2off, float (&acc)[4][3][4]){
    #pragma unroll
    for (int c = 0; c < 3; c++)
        gru_chunk<G2>(wbuf + c*9216, a_h, a_l, kbase + c, b4off, bt2off, bx2off, acc);
}

__device__ __forceinline__ void gru_epilogue(
    int p, float (&acc)[4][3][4], const float* sb,
    const unsigned* Ahw, const unsigned* Alw, float* hout,
    int comp, int row0, int wm, int wn, int lr, int lq)
{
    #pragma unroll
    for (int t = 0; t < 3; t++){
        int f0 = p*48 + wn*24 + t*8 + 2*lq;
        float bR0 = sb[f0],       bR1 = sb[f0+1];
        float bZ0 = sb[96+f0],    bZ1 = sb[96+f0+1];
        float bI0 = sb[192+f0],   bI1 = sb[192+f0+1];
        float bN0 = sb[288+f0],   bN1 = sb[288+f0+1];
        #pragma unroll
        for (int half = 0; half < 2; half++){
            int row = wm*16 + lr + half*8;
            size_t base = (size_t)(comp*NC + row0 + row)*96;
            int wofs = row*100 + 48 + (f0 >> 1);
            unsigned hw = Ahw[wofs], lw = Alw[wofs];
            float hx = bflo(hw) + bflo(lw);
            float hy = bfhi(hw) + bfhi(lw);
            int ci = half*2;
            float xr0 = fminf(fmaxf((acc[0][t][ci]   + bR0)*L2E, -30.f), 30.f);
            float xr1 = fminf(fmaxf((acc[0][t][ci+1] + bR1)*L2E, -30.f), 30.f);
            float xz0 = fminf(fmaxf((acc[1][t][ci]   + bZ0)*L2E, -30.f), 30.f);
            float xz1 = fminf(fmaxf((acc[1][t][ci+1] + bZ1)*L2E, -30.f), 30.f);
            float er0 = ex2f(xr0), er1 = ex2f(xr1);
            float ez0 = ex2f(xz0), ez1 = ex2f(xz1);
            float d1 = er0 + 1.f, d2 = ez0 + 1.f, d3 = er1 + 1.f, d4 = ez1 + 1.f;
            float p12 = d1*d2, p34 = d3*d4;
            float rp = rcpf(p12*p34);
            float q12 = rp*p34, q34 = rp*p12;
            float rr0 = er0*(q12*d2), zz0 = ez0*(q12*d1);
            float rr1 = er1*(q34*d4), zz1 = ez1*(q34*d3);
            float t0 = fmaf(rr0, acc[3][t][ci]   + bN0, acc[2][t][ci]   + bI0);
            float t1 = fmaf(rr1, acc[3][t][ci+1] + bN1, acc[2][t][ci+1] + bI1);
            float lt0 = fminf(fmaxf(t0*(2.f*L2E), -30.f), 30.f);
            float lt1 = fminf(fmaxf(t1*(2.f*L2E), -30.f), 30.f);
            float e0 = ex2f(lt0), e1 = ex2f(lt1);
            float dt0 = e0 + 1.f, dt1 = e1 + 1.f;
            float rpt = rcpf(dt0*dt1);
            float nn0 = fmaf(-2.f, rpt*dt1, 1.f);
            float nn1 = fmaf(-2.f, rpt*dt0, 1.f);
            float o0 = fmaf(zz0, hx - nn0, nn0);
            float o1 = fmaf(zz1, hy - nn1, nn1);
            *(float2*)(hout + base + f0) = make_float2(o0, o1);
        }
    }
}

template<int WARM>
__global__ void __launch_bounds__(256, 2) k_gru(int layer){
    extern __shared__ char smc[];
    const uint32_t smb = smem_u32(smc);
    float* sb = (float*)(smc + BIAS_OFF);

    const int comp = blockIdx.y;
    const int cl = comp*6 + layer;
    const int row0 = blockIdx.x*64;
    const int tid = threadIdx.x;
    const int lane = tid & 31;
    const int wid = tid >> 5;
    const int wm = wid & 3;          // rows wm*16..+15
    const int wn = wid >> 2;         // 0..1
    const int lr = lane >> 2;        // 0..7
    const int lq = lane & 3;         // 0..3

    const unsigned* wsrc = g_Wp + (size_t)cl*55296;
    const uint32_t w0 = smb + W_OFF;
    const uint32_t w1 = w0 + W_BUF;

    // kick off W fills (overlap the gather)
    fill3(w0, wsrc, tid);
    fill3(w1, wsrc + 3*2304, tid);

    for (int i = tid; i < 384; i += 256) sb[i] = g_bias[cl*384 + i];

    const float* hin  = WARM ? g_h : ((layer & 1) ? g_s : g_h);
    float*       hout = WARM ? g_s : ((layer & 1) ? g_h : g_s);

    // ---- wave-parallel gather + stage A: float4 row loads (lanes 0-23) ----
    {
        unsigned* Ahw2 = (unsigned*)(smc + A_HI_OFF);
        unsigned* Alw2 = (unsigned*)(smc + A_LO_OFF);
        const int nd = comp*NC + row0 + wid*8;
        const bool act = (lane < 24);
        float4 s4[8];
        #pragma unroll
        for (int r = 0; r < 8; r++) s4[r] = make_float4(0.f,0.f,0.f,0.f);
        if (!WARM){
            int beg[8], end8[8];
            #pragma unroll
            for (int r = 0; r < 8; r++){
                int node = nd + r;
                beg[r] = __ldg(&g_off[node]) + __ldg(&g_part[node >> 10]);
            }
            #pragma unroll
            for (int r = 0; r < 8; r++){
                int n1 = nd + r + 1;
                end8[r] = (n1 == NN) ? EE : (__ldg(&g_off[n1]) + __ldg(&g_part[n1 >> 10]));
            }
            int md = 0;
            #pragma unroll
            for (int r = 0; r < 8; r++) md = max(md, end8[r] - beg[r]);
            for (int j = 0; j < md; j++){
                int sidx[8];
                #pragma unroll
                for (int r = 0; r < 8; r++)
                    sidx[r] = (j < end8[r] - beg[r]) ? __ldg(&g_esrc[beg[r] + j]) : -1;
                #pragma unroll
                for (int r = 0; r < 8; r++){
                    if (sidx[r] >= 0 && act){
                        float4 v = __ldg((const float4*)(hin + (size_t)sidx[r]*96) + lane);
                        s4[r].x += v.x; s4[r].y += v.y; s4[r].z += v.z; s4[r].w += v.w;
                    }
                }
            }
        }
        // batch h-row loads (all independent)
        float4 h4[8];
        #pragma unroll
        for (int r = 0; r < 8; r++){
            h4[r] = make_float4(0.f,0.f,0.f,0.f);
            if (act) h4[r] = __ldg((const float4*)(hin + (size_t)(nd + r)*96) + lane);
        }
        #pragma unroll
        for (int r = 0; r < 8; r++){
            if (act){
                int row = wid*8 + r;
                int wb = row*100 + 2*lane;
                unsigned hi, lo;
                pack2(s4[r].x, s4[r].y, hi, lo);
                Ahw2[wb] = hi;      Alw2[wb] = lo;
                pack2(s4[r].z, s4[r].w, hi, lo);
                Ahw2[wb + 1] = hi;  Alw2[wb + 1] = lo;
                pack2(h4[r].x, h4[r].y, hi, lo);
                Ahw2[wb + 48] = hi; Alw2[wb + 48] = lo;
                pack2(h4[r].z, h4[r].w, hi, lo);
                Ahw2[wb + 49] = hi; Alw2[wb + 49] = lo;
            }
        }
    }

    // per-warp ldmatrix addresses
    const uint32_t a_h = smb + A_HI_OFF +
        ((wm*16 + (lane & 15))*100 + ((lane >> 4) << 2))*4;
    const uint32_t a_l = a_h + (A_LO_OFF - A_HI_OFF);
    const int hsel = (lane >> 3) & 1;
    const uint32_t b4off  = wn*768 + swzoff(((lane >> 4) << 3) + (lane & 7), hsel);
    const uint32_t bt2off = (lane >> 4)*1536 + wn*768 + swzoff(16 + (lane & 7), hsel);
    const uint32_t bx2off = 3072 + wn*768 + swzoff(16 + (lane & 7), hsel);

    const unsigned* Ahw = (const unsigned*)(smc + A_HI_OFF);
    const unsigned* Alw = (const unsigned*)(smc + A_LO_OFF);

    // boundary: all-done-X barrier, refill X, ensure Y ready+visible
    #define BOUNDARY(bufaddr, srcoff) do { \
        __syncthreads(); \
        fill3(bufaddr, wsrc + (srcoff)*2304, tid); \
        CP_WAITG(1); \
        __syncthreads(); \
    } while(0)

    float acc[4][3][4];
    #pragma unroll
    for (int g = 0; g < 4; g++)
        #pragma unroll
        for (int t = 0; t < 3; t++)
            #pragma unroll
            for (int i = 0; i < 4; i++) acc[g][t][i] = 0.f;

    CP_WAITG(1);
    __syncthreads();   // A staged + W0 ready

    compute3<2>(w0, a_h, a_l, 0, b4off, bt2off, bx2off, acc);
    BOUNDARY(w0, 6);
    compute3<2>(w1, a_h, a_l, 3, b4off, bt2off, bx2off, acc);
    BOUNDARY(w1, 9);
    compute3<3>(w0, a_h, a_l, 6, b4off, bt2off, bx2off, acc);
    BOUNDARY(w0, 12);
    compute3<3>(w1, a_h, a_l, 9, b4off, bt2off, bx2off, acc);
    BOUNDARY(w1, 15);
    gru_epilogue(0, acc, sb, Ahw, Alw, hout, comp, row0, wm, wn, lr, lq);

    #pragma unroll
    for (int g = 0; g < 4; g++)
        #pragma unroll
        for (int t = 0; t < 3; t++)
            #pragma unroll
            for (int i = 0; i < 4; i++) acc[g][t][i] = 0.f;

    compute3<2>(w0, a_h, a_l, 0, b4off, bt2off, bx2off, acc);
    BOUNDARY(w0, 18);
    compute3<2>(w1, a_h, a_l, 3, b4off, bt2off, bx2off, acc);
    BOUNDARY(w1, 21);
    compute3<3>(w0, a_h, a_l, 6, b4off, bt2off, bx2off, acc);
    __syncthreads();
    CP_WAITG(0);
    __syncthreads();
    compute3<3>(w1, a_h, a_l, 9, b4off, bt2off, bx2off, acc);
    gru_epilogue(1, acc, sb, Ahw, Alw, hout, comp, row0, wm, wn, lr, lq);
    #undef BOUNDARY
}

// ---------------- pooling: mean of relu(h) over sorted batch ranges ---------
__global__ void k_pool(const int* __restrict__ b1, const int* __restrict__ b2,
                       const int* __restrict__ b3){
    int b = blockIdx.x;
    int c = blockIdx.y;
    const int* batch = (c==0)?b1:((c==1)?b2:b3);
    int lo = 0, hi = NC;
    while (lo < hi){ int m = (lo+hi) >> 1; if (batch[m] < b) lo = m+1; else hi = m; }
    int s0 = lo;
    hi = NC;
    while (lo < hi){ int m = (lo+hi) >> 1; if (batch[m] < b+1) lo = m+1; else hi = m; }
    int e0 = lo;
    float denom = fmaxf((float)(e0 - s0), 1.f);
    int f = threadIdx.x;
    float sum = 0.f;
    for (int n = s0; n < e0; n++)
        sum += fmaxf(g_h[(size_t)(c*NC + n)*HD + f], 0.f);
    g_pool[((size_t)c*NB + b)*HD + f] = sum / denom;
}

// ---------------- feature assembly ------------------------------------------
__global__ void k_feat(){
    int idx = blockIdx.x*blockDim.x + threadIdx.x;
    if (idx >= NB*384) return;
    int b = idx / 384;
    int j = idx - b*384;
    float v;
    if (j < 96)       v = g_pool[(size_t)b*HD + j];
    else if (j < 192) v = g_pool[((size_t)NB + b)*HD + (j-96)];
    else if (j < 288) v = g_pool[((size_t)2*NB + b)*HD + (j-192)];
    else {
        int jj = j - 288;
        v = g_pool[(size_t)b*HD + jj]
          * g_pool[((size_t)NB + b)*HD + jj]
          * g_pool[((size_t)2*NB + b)*HD + jj];
    }
    g_feat[idx] = v;
}

// ---------------- MLP GEMM (f32x2 FFMA2, globals resolved in device code) ---
template<int MODE>
__global__ void __launch_bounds__(256) k_gemm(const float* __restrict__ B,
                                              const float* __restrict__ bias){
    const float* A = (MODE == 0) ? g_feat : g_t1;
    float*       C = (MODE == 0) ? g_t1   : g_t2;
    const int N = (MODE == 0) ? 1536 : 384;
    const int K = (MODE == 0) ? 384  : 1536;

    __shared__ float As[64*33];
    __shared__ __align__(16) float Bs[32*68];
    int txx = threadIdx.x & 15;
    int tyy = threadIdx.x >> 4;
    int m0 = blockIdx.y*64;
    int n0 = blockIdx.x*64;
    unsigned long long acc2[4][2];
    #pragma unroll
    for (int i = 0; i < 4; i++){ acc2[i][0] = 0ull; acc2[i][1] = 0ull; }

    for (int kc = 0; kc < K; kc += 32){
        __syncthreads();
        for (int i = threadIdx.x; i < 64*32; i += 256){
            int r = i >> 5, k = i & 31;
            As[r*33 + k] = A[(size_t)(m0 + r)*K + kc + k];
        }
        for (int i = threadIdx.x; i < 32*64; i += 256){
            int k = i >> 6, cc = i & 63;
            Bs[k*68 + cc] = B[(size_t)(kc + k)*N + n0 + cc];
        }
        __syncthreads();
        #pragma unroll 8
        for (int k = 0; k < 32; k++){
            unsigned long long b0 = *(const unsigned long long*)&Bs[k*68 + txx*4];
            unsigned long long b1 = *(const unsigned long long*)&Bs[k*68 + txx*4 + 2];
            #pragma unroll
            for (int i = 0; i < 4; i++){
                unsigned long long ai = dup2(As[(tyy*4 + i)*33 + k]);
                acc2[i][0] = ffma2(ai, b0, acc2[i][0]);
                acc2[i][1] = ffma2(ai, b1, acc2[i][1]);
            }
        }
    }
    #pragma unroll
    for (int i = 0; i < 4; i++){
        int row = m0 + tyy*4 + i;
        #pragma unroll
        for (int j2 = 0; j2 < 2; j2++){
            float2 v = unpk2(acc2[i][j2]);
            int col = n0 + txx*4 + j2*2;
            C[(size_t)row*N + col]     = fmaxf(v.x + bias[col], 0.f);
            C[(size_t)row*N + col + 1] = fmaxf(v.y + bias[col+1], 0.f);
        }
    }
}

// ---------------- fc3: [4096,384] @ [384,3] ---------------------------------
__global__ void k_fc3(const float* __restrict__ w, const float* __restrict__ b,
                      float* __restrict__ out){
    int gt = blockIdx.x*blockDim.x + threadIdx.x;
    int row = gt >> 5;
    int lane = gt & 31;
    if (row >= NB) return;
    float a0 = 0.f, a1 = 0.f, a2 = 0.f;
    for (int k = lane; k < 384; k += 32){
        float f = g_t2[(size_t)row*384 + k];
        a0 += f*w[k*3 + 0];
        a1 += f*w[k*3 + 1];
        a2 += f*w[k*3 + 2];
    }
    #pragma unroll
    for (int o = 16; o; o >>= 1){
        a0 += __shfl_down_sync(0xffffffffu, a0, o);
        a1 += __shfl_down_sync(0xffffffffu, a1, o);
        a2 += __shfl_down_sync(0xffffffffu, a2, o);
    }
    if (lane == 0){
        out[row*3 + 0] = a0 + b[0];
        out[row*3 + 1] = a1 + b[1];
        out[row*3 + 2] = a2 + b[2];
    }
}

// ---------------- launch ----------------------------------------------------
extern "C" void kernel_launch(void* const* d_in, const int* in_sizes, int n_in,
                              void* d_out, int out_size) {
    const float* xs[3]   = {0,0,0};
    const int*   es[3]   = {0,0,0};
    const int*   bs[3]   = {0,0,0};
    const float* Ws[3]   = {0,0,0};
    const float* wihs[3] = {0,0,0};
    const float* whhs[3] = {0,0,0};
    const float* bihs[3] = {0,0,0};
    const float* bhhs[3] = {0,0,0};
    const float* fcw[2]  = {0,0};
    const float* fc1b = 0; const float* fc2b = 0;
    const float* fc3w = 0; const float* fc3b = 0;
    int nx=0, ne=0, nb=0, nW=0, nwpair=0, nbpair=0, nfcw=0;
    for (int i = 0; i < n_in; i++){
        int s = in_sizes[i];
        const void* p = d_in[i];
        switch (s){
            case 6400000: if (nx < 3) xs[nx++] = (const float*)p; break;
            case 800000:  if (ne < 3) es[ne++] = (const int*)p;   break;
            case 200000:  if (nb < 3) bs[nb++] = (const int*)p;   break;
            case 55296:   if (nW < 3) Ws[nW++] = (const float*)p; break;
            case 27648:   { int c = nwpair/2;
                            if (c < 3){ if ((nwpair & 1) == 0) wihs[c] = (const float*)p;
                                        else                   whhs[c] = (const float*)p; }
                            nwpair++; } break;
            case 288:     { int c = nbpair/2;
                            if (c < 3){ if ((nbpair & 1) == 0) bihs[c] = (const float*)p;
                                        else                   bhhs[c] = (const float*)p; }
                            nbpair++; } break;
            case 589824:  if (nfcw < 2) fcw[nfcw++] = (const float*)p; break;
            case 1536:    fc1b = (const float*)p; break;
            case 384:     fc2b = (const float*)p; break;
            case 1152:    fc3w = (const float*)p; break;
            case 3:       fc3b = (const float*)p; break;
            default: break;
        }
    }
    const float* fc1w = fcw[0];
    const float* fc2w = fcw[1];
    float* out = (float*)d_out;

    cudaFuncSetAttribute(k_gru<0>, cudaFuncAttributeMaxDynamicSharedMemorySize, SMEM_GRU_TOTAL);
    cudaFuncSetAttribute(k_gru<1>, cudaFuncAttributeMaxDynamicSharedMemorySize, SMEM_GRU_TOTAL);

    // 1: mega init (h0 + counters + W prepack + bias pack)
    k_mega<<<MEGA_IB + MEGA_PB + MEGA_BB, 256>>>(
        xs[0], xs[1], xs[2],
        Ws[0], wihs[0], whhs[0], Ws[1], wihs[1], whhs[1], Ws[2], wihs[2], whhs[2],
        bihs[0], bhhs[0], bihs[1], bhhs[1], bihs[2], bhhs[2]);
    // 2-3: CSR histogram + block scan
    k_deg<<<(EE + 255)/256, 256>>>(es[0], es[1], es[2]);
    k_scan1<<<NPART, SCAN_BLK>>>();
    // 4: telemetry warmup GRU (no gather; writes g_s, overwritten by layer 0)
    k_gru<1><<<dim3(64, 3), 256, SMEM_GRU_TOTAL>>>(0);
    // 5-6: finish CSR
    k_scan2<<<1, SCAN_BLK>>>();
    k_fill<<<(EE + 255)/256, 256>>>(es[0], es[1], es[2]);

    const int gruBlocks = NC/64;   // 3125
    for (int l = 0; l < 6; l++)
        k_gru<0><<<dim3(gruBlocks, 3), 256, SMEM_GRU_TOTAL>>>(l);

    k_pool<<<dim3(NB, 3), 96>>>(bs[0], bs[1], bs[2]);
    k_feat<<<(NB*384 + 255)/256, 256>>>();
    k_gemm<0><<<dim3(1536/64, NB/64), 256>>>(fc1w, fc1b);
    k_gemm<1><<<dim3(384/64,  NB/64), 256>>>(fc2w, fc2b);
    k_fc3<<<(NB*32 + 255)/256, 256>>>(fc3w, fc3b, out);
}